// round 17
// baseline (speedup 1.0000x reference)
#include <cuda_runtime.h>
#include <cuda_bf16.h>
#include <cuda_fp16.h>

#define BB   32
#define TT   96
#define HID  256
#define CE   400
#define VV   256
#define HH_  16
#define WW_  64
#define AA   256
#define HW   1024
#define NZ   4          // a-chunks (scan)
#define ACH  64         // a per scan block
#define SGRID 128       // scan grid: 32 b x 4 zc
#define NBLK_B 4        // blocks per batch
#define EP2STR 516      // padded row stride (words) for sEP (full image)

// dynamic smem layout (bytes)
#define SM_EP   0
#define SM_COV  132096              // 64*516*4
#define SM_E    (SM_COV + 5440)     // 20*68*4
#define SM_Q    (SM_E + 4096)
#define SM_RED  (SM_Q + 512)        // 64 floats (raw q) + 64 words (packed q)
#define SM_TOT  (SM_RED + 32)

// ---------------- device scratch ----------------
__device__ __align__(16) float g_x0[BB*TT*HID];
__device__ __align__(16) float g_x1[BB*TT*HID];
__device__ __align__(16) __half g_wgh[3*512*768];     // f16 glu weights, [layer][o][k*256+ic]
__device__ __align__(16) float g_WhT[HID*AA];
__device__ __align__(16) __half g_fcWh[VV*(HID+CE)];  // f16 fc weights row-major
__device__ __align__(16) __half g_Wh[AA*32];          // plain f16 W_cov, taps 25..31 = 0
__device__ __align__(16) unsigned g_EPh[BB*8*2*8192]; // f16x2 EP, [slab32][(a&31)*256 + px/2]
__device__ __align__(16) float g_QB[BB*TT*AA];        // q + b_h + b_cov
__device__ __align__(16) float g_epart[2*NZ*BB*HW];   // double-buffered partial e
__device__ __align__(16) float g_alpha[BB*TT*HW];
__device__ __align__(16) float g_ctxall[BB*TT*CE];

// per-batch barrier state (128B padded)
__device__ unsigned g_barC[BB*32];
__device__ unsigned g_barG[BB*32];

__device__ __forceinline__ float sigmoid_fast(float x) {
    return __fdividef(1.f, 1.f + __expf(-x));
}

// ---- packed helpers (sm_103a) ----
typedef unsigned long long u64;
__device__ __forceinline__ unsigned pk_h2(float lo, float hi) {
    unsigned d;
    asm("cvt.rn.f16x2.f32 %0, %1, %2;" : "=r"(d) : "f"(hi), "f"(lo));
    return d;
}
__device__ __forceinline__ unsigned tanh2_hw(unsigned s) {
    unsigned d; asm("tanh.approx.f16x2 %0, %1;" : "=r"(d) : "r"(s)); return d;
}
__device__ __forceinline__ unsigned hfma2(unsigned a, unsigned b, unsigned c) {
    unsigned d;
    asm("fma.rn.f16x2 %0, %1, %2, %3;" : "=r"(d) : "r"(a), "r"(b), "r"(c));
    return d;
}
__device__ __forceinline__ unsigned hadd2(unsigned a, unsigned b) {
    unsigned d;
    asm("add.rn.f16x2 %0, %1, %2;" : "=r"(d) : "r"(a), "r"(b));
    return d;
}
__device__ __forceinline__ void h2f2(unsigned h, float& lo, float& hi) {
    asm("{.reg .b16 l, hh; mov.b32 {l, hh}, %2; cvt.f32.f16 %0, l; cvt.f32.f16 %1, hh;}"
        : "=f"(lo), "=f"(hi) : "r"(h));
}
__device__ __forceinline__ void mma16816(float& c0, float& c1, float& c2, float& c3,
                                         unsigned a0, unsigned a1, unsigned a2, unsigned a3,
                                         unsigned b0, unsigned b1) {
    asm("mma.sync.aligned.m16n8k16.row.col.f32.f16.f16.f32 "
        "{%0,%1,%2,%3}, {%4,%5,%6,%7}, {%8,%9}, {%0,%1,%2,%3};"
        : "+f"(c0), "+f"(c1), "+f"(c2), "+f"(c3)
        : "r"(a0), "r"(a1), "r"(a2), "r"(a3), "r"(b0), "r"(b1));
}

// ---------------- prep ----------------
__global__ void __launch_bounds__(256) prep_kernel(const int* __restrict__ tgt,
                            const float* __restrict__ embed,
                            const float* __restrict__ w1,
                            const float* __restrict__ w2,
                            const float* __restrict__ w3,
                            const float* __restrict__ W_h,
                            const float* __restrict__ fc_W,
                            const float* __restrict__ W_cov) {
    int idx = blockIdx.x * 256 + threadIdx.x;
    if (idx < BB*TT*HID) {
        int bt = idx >> 8;
        g_x0[idx] = embed[tgt[bt]*HID + (idx & 255)];
    }
    if (idx < 3*512*768) {
        int layer = idx / (512*768);
        int rem = idx % (512*768);
        int o = rem / 768, kk = rem % 768;
        int k = kk >> 8, ic = kk & 255;
        const float* w = (layer == 0) ? w1 : (layer == 1) ? w2 : w3;
        g_wgh[idx] = __float2half(w[o*768 + ic*3 + k]);
    }
    if (idx < AA*HID) {
        int a = idx >> 8, h = idx & 255;
        g_WhT[h*AA + a] = W_h[idx];
    }
    if (idx < VV*(HID+CE)) {
        g_fcWh[idx] = __float2half(fc_W[idx]);
    }
    if (idx < AA*32) {
        int a = idx >> 5, k = idx & 31;
        g_Wh[idx] = __float2half((k < 25) ? W_cov[a*25 + k] : 0.f);
    }
}

// ---------------- causal GLU layer via HMMA (shared X tile across 3 taps) ----------------
__global__ void __launch_bounds__(256) glu_kernel(int src_sel, int layer,
                                                  const float* __restrict__ bias) {
    const float* xin  = src_sel ? g_x1 : g_x0;
    float*       xout = src_sel ? g_x0 : g_x1;
    const unsigned* wW = (const unsigned*)g_wgh + layer*(512*768/2);

    int b  = blockIdx.x;
    int o0 = blockIdx.y * 32;
    int t0 = blockIdx.z * 48;
    __shared__ unsigned sW3[3][64][9];
    __shared__ unsigned sX[50][9];
    __shared__ float    sY[64][51];
    int tid = threadIdx.x, lane = tid & 31, warp = tid >> 5;
    int ln4 = lane & 3, lnr = lane >> 2;
    int mt = warp >> 1;
    int nbase = (warp & 1) * 3;
    int rL = mt*16 + lnr, rH = rL + 8;

    float acc[3][4];
#pragma unroll
    for (int nt = 0; nt < 3; nt++)
#pragma unroll
        for (int i = 0; i < 4; i++) acc[nt][i] = 0.f;

    for (int is = 0; is < 16; is++) {
        __syncthreads();
#pragma unroll
        for (int rep = 0; rep < 6; rep++) {
            int w = tid + rep*256;
            int k = w >> 9, r = (w >> 3) & 63, jp = w & 7;
            int wr = (r < 32) ? (o0 + r) : (256 + o0 + r - 32);
            sW3[k][r][jp] = wW[wr*384 + k*128 + is*8 + jp];
        }
        for (int idx = tid; idx < 400; idx += 256) {
            int tl = idx >> 3, jp = idx & 7;
            int tg = t0 + tl - 2;
            unsigned v = 0u;
            if (tg >= 0 && tg < TT) {
                float2 f = *(const float2*)&xin[(b*TT + tg)*HID + is*16 + jp*2];
                v = pk_h2(f.x, f.y);
            }
            sX[tl][jp] = v;
        }
        __syncthreads();

#pragma unroll
        for (int k = 0; k < 3; k++) {
            unsigned a0 = sW3[k][rL][ln4],     a1 = sW3[k][rH][ln4];
            unsigned a2 = sW3[k][rL][ln4 + 4], a3 = sW3[k][rH][ln4 + 4];
#pragma unroll
            for (int nt = 0; nt < 3; nt++) {
                int tr = (nbase + nt)*8 + lnr + k;
                unsigned b0 = sX[tr][ln4], b1 = sX[tr][ln4 + 4];
                mma16816(acc[nt][0], acc[nt][1], acc[nt][2], acc[nt][3],
                         a0, a1, a2, a3, b0, b1);
            }
        }
    }

#pragma unroll
    for (int nt = 0; nt < 3; nt++) {
        int tc = (nbase + nt)*8 + ln4*2;
        sY[rL][tc]     = acc[nt][0];
        sY[rL][tc + 1] = acc[nt][1];
        sY[rH][tc]     = acc[nt][2];
        sY[rH][tc + 1] = acc[nt][3];
    }
    __syncthreads();
    for (int idx = tid; idx < 32*48; idx += 256) {
        int r = idx & 31, tl = idx >> 5;
        float av = sY[r][tl]      + bias[o0 + r];
        float gv = sY[r + 32][tl] + bias[256 + o0 + r];
        xout[(b*TT + t0 + tl)*HID + o0 + r] = av * sigmoid_fast(gv);
    }
}

// ---------------- enc_proj: HMMA  EP[a,px] = W_enc @ enc_feat + b_enc -> f16 ----------------
__global__ void __launch_bounds__(256) encproj_kernel(const float* __restrict__ enc_feat,
                                                      const float* __restrict__ W_enc,
                                                      const float* __restrict__ b_enc) {
    int b = blockIdx.x, a0 = blockIdx.y*64, p0 = blockIdx.z*64;
    __shared__ unsigned sWh[64][9];
    __shared__ unsigned sFt[64][9];
    int tid = threadIdx.x, lane = tid & 31, warp = tid >> 5;
    int ln4 = lane & 3, lnr = lane >> 2;
    int m  = warp >> 1;
    int nb = (warp & 1) * 4;

    float acc[4][4];
#pragma unroll
    for (int nt = 0; nt < 4; nt++)
#pragma unroll
        for (int i = 0; i < 4; i++) acc[nt][i] = 0.f;

    for (int ks = 0; ks < 25; ks++) {
        int c0 = ks*16;
        __syncthreads();
#pragma unroll
        for (int rep = 0; rep < 2; rep++) {
            int w = tid + rep*256;
            int a = w >> 3, kp = w & 7;
            float2 wv = *(const float2*)&W_enc[(a0 + a)*CE + c0 + kp*2];
            sWh[a][kp] = pk_h2(wv.x, wv.y);
        }
#pragma unroll
        for (int rep = 0; rep < 2; rep++) {
            int w = tid + rep*256;
            int px = w & 63, kp = w >> 6;
            float f0 = enc_feat[((size_t)b*CE + c0 + kp*2    )*HW + p0 + px];
            float f1 = enc_feat[((size_t)b*CE + c0 + kp*2 + 1)*HW + p0 + px];
            sFt[px][kp] = pk_h2(f0, f1);
        }
        __syncthreads();

        int rL = m*16 + lnr, rH = rL + 8;
        unsigned af0 = sWh[rL][ln4],     af1 = sWh[rH][ln4];
        unsigned af2 = sWh[rL][ln4 + 4], af3 = sWh[rH][ln4 + 4];
#pragma unroll
        for (int nt = 0; nt < 4; nt++) {
            int pxr = (nb + nt)*8 + lnr;
            unsigned b0 = sFt[pxr][ln4], b1 = sFt[pxr][ln4 + 4];
            mma16816(acc[nt][0], acc[nt][1], acc[nt][2], acc[nt][3],
                     af0, af1, af2, af3, b0, b1);
        }
    }

    int aL = a0 + m*16 + lnr, aH = aL + 8;
    float beL = b_enc[aL], beH = b_enc[aH];
    int slab_p = p0 >> 9;
#pragma unroll
    for (int nt = 0; nt < 4; nt++) {
        int pxc = p0 + (nb + nt)*8 + ln4*2;
        int wofs = ((pxc & 511) >> 1);
        {
            int slab = (b*8 + (aL >> 5))*2 + slab_p;
            g_EPh[slab*8192 + (aL & 31)*256 + wofs] = pk_h2(acc[nt][0] + beL, acc[nt][1] + beL);
        }
        {
            int slab = (b*8 + (aH >> 5))*2 + slab_p;
            g_EPh[slab*8192 + (aH & 31)*256 + wofs] = pk_h2(acc[nt][2] + beH, acc[nt][3] + beH);
        }
    }
}

// ---------------- q precompute ----------------
__global__ void __launch_bounds__(256) qgemm_kernel(const float* __restrict__ b_h,
                                                    const float* __restrict__ b_cov) {
    int m0 = blockIdx.x * 64;
    int n0 = blockIdx.y * 64;
    __shared__ float Hs[16][66];
    __shared__ float Ws[16][64];
    int tid = threadIdx.x;
    int tm = (tid & 15)*4, tn = (tid >> 4)*4;
    float acc[4][4];
#pragma unroll
    for (int r = 0; r < 4; r++)
#pragma unroll
        for (int c = 0; c < 4; c++) acc[r][c] = 0.f;

    for (int k0 = 0; k0 < HID; k0 += 16) {
        __syncthreads();
        for (int idx = tid; idx < 1024; idx += 256) {
            int kk = idx & 15, m = idx >> 4;
            Hs[kk][m] = g_x1[(m0 + m)*HID + k0 + kk];
        }
        for (int idx = tid; idx < 1024; idx += 256) {
            int i = idx & 63, kk = idx >> 6;
            Ws[kk][i] = g_WhT[(k0 + kk)*AA + n0 + i];
        }
        __syncthreads();
#pragma unroll
        for (int kk = 0; kk < 16; kk++) {
            float hv[4], wv[4];
#pragma unroll
            for (int r = 0; r < 4; r++) hv[r] = Hs[kk][tm + r];
#pragma unroll
            for (int c = 0; c < 4; c++) wv[c] = Ws[kk][tn + c];
#pragma unroll
            for (int r = 0; r < 4; r++)
#pragma unroll
                for (int c = 0; c < 4; c++)
                    acc[r][c] = fmaf(hv[r], wv[c], acc[r][c]);
        }
    }
#pragma unroll
    for (int r = 0; r < 4; r++)
#pragma unroll
        for (int c = 0; c < 4; c++) {
            int n = n0 + tn + c;
            g_QB[(m0 + tm + r)*AA + n] = acc[r][c] + b_h[n] + b_cov[n];
        }
}

// ---------------- persistent scan: 4 blocks/batch (64 a each), 1 block/SM, dynamic smem ----------------
extern __shared__ __align__(16) char s_dyn[];
__global__ void __launch_bounds__(256, 1) scan_kernel(const float* __restrict__ v_attn) {
    int bid = blockIdx.x;
    int b   = bid >> 2;
    int zc  = bid & 3;
    int a0  = zc * ACH;

    unsigned* sEP  = (unsigned*)(s_dyn + SM_EP);    // [64][EP2STR]
    float (*sCov)[68] = (float (*)[68])(s_dyn + SM_COV);  // rows -2..17
    float*    sE   = (float*)(s_dyn + SM_E);
    float*    sQf  = (float*)(s_dyn + SM_Q);         // raw q values (64)
    unsigned* sQh  = (unsigned*)(s_dyn + SM_Q) + 64; // packed (q,q) (64)
    float*    reds = (float*)(s_dyn + SM_RED);

    int tid = threadIdx.x, lane = tid & 31, warp = tid >> 5;
    int ln4 = lane & 3, lnr = lane >> 2;
    int wpx = warp * 128;

    for (int i = tid; i < 8192; i += 256) {
        int word = i*4;
        int a = word >> 9, px2 = word & 511;
        int strip = px2 >> 8, wofs = px2 & 255;
        int slab = (b*8 + zc*2 + (a >> 5))*2 + strip;
        uint4 v = *(const uint4*)&g_EPh[slab*8192 + (a & 31)*256 + wofs];
        *(uint4*)&sEP[a*EP2STR + px2] = v;
    }
    for (int i = tid; i < 20*68; i += 256) ((float*)sCov)[i] = 0.f;

    unsigned af[4][2][4];
#pragma unroll
    for (int mt = 0; mt < 4; mt++)
#pragma unroll
        for (int kt = 0; kt < 2; kt++) {
            int rL = a0 + mt*16 + lnr, rH = rL + 8;
            int kc = kt*16 + ln4*2;
            af[mt][kt][0] = *(const unsigned*)&g_Wh[rL*32 + kc];
            af[mt][kt][1] = *(const unsigned*)&g_Wh[rH*32 + kc];
            af[mt][kt][2] = *(const unsigned*)&g_Wh[rL*32 + kc + 8];
            af[mt][kt][3] = *(const unsigned*)&g_Wh[rH*32 + kc + 8];
        }
    unsigned vreg[8];
#pragma unroll
    for (int m = 0; m < 8; m++) {
        float v = v_attn[a0 + lnr + m*8];
        vreg[m] = pk_h2(v, v);
    }
    int goff[8]; bool gval[8];
#pragma unroll
    for (int kt = 0; kt < 2; kt++)
#pragma unroll
        for (int pos = 0; pos < 4; pos++) {
            int j = kt*4 + pos;
            int k = kt*16 + ln4*2 + (pos & 1) + ((pos & 2) ? 8 : 0);
            gval[j] = (k < 25);
            goff[j] = ((k/5)*68 + (k%5));
        }

    if (tid < ACH) sQf[tid] = g_QB[(b*TT + 0)*AA + a0 + tid];

    for (int t = 0; t < TT; t++) {
        int ping = t & 1;
        if (tid < ACH) {
            float q = sQf[tid];
            sQh[tid] = pk_h2(q, q);
        }
        __syncthreads();

        unsigned qreg[8];
#pragma unroll
        for (int m = 0; m < 8; m++) qreg[m] = sQh[lnr + m*8];

#pragma unroll 2
        for (int nt = 0; nt < 16; nt++) {
            int n0 = wpx + nt*8;
            int px = n0 + lnr;
            int py = px >> 6, pxx = px & 63;
            const float* cb = &sCov[py][pxx];
            float gv[8];
#pragma unroll
            for (int j = 0; j < 8; j++)
                gv[j] = gval[j] ? cb[goff[j]] : 0.f;
            unsigned b00 = pk_h2(gv[0], gv[1]), b01 = pk_h2(gv[2], gv[3]);
            unsigned b10 = pk_h2(gv[4], gv[5]), b11 = pk_h2(gv[6], gv[7]);
            int epc = (n0 >> 1) + ln4;

            unsigned eacc = 0u;
#pragma unroll
            for (int mt = 0; mt < 4; mt++) {
                float c0 = 0.f, c1 = 0.f, c2 = 0.f, c3 = 0.f;
                mma16816(c0, c1, c2, c3,
                         af[mt][0][0], af[mt][0][1], af[mt][0][2], af[mt][0][3], b00, b01);
                mma16816(c0, c1, c2, c3,
                         af[mt][1][0], af[mt][1][1], af[mt][1][2], af[mt][1][3], b10, b11);
                int rowL = mt*16 + lnr, rowH = rowL + 8;
                unsigned sL = pk_h2(c0, c1);
                sL = hadd2(sL, sEP[rowL*EP2STR + epc]);
                sL = hadd2(sL, qreg[mt*2]);
                eacc = hfma2(tanh2_hw(sL), vreg[mt*2], eacc);
                unsigned sH = pk_h2(c2, c3);
                sH = hadd2(sH, sEP[rowH*EP2STR + epc]);
                sH = hadd2(sH, qreg[mt*2 + 1]);
                eacc = hfma2(tanh2_hw(sH), vreg[mt*2 + 1], eacc);
            }
            eacc = hadd2(eacc, __shfl_xor_sync(~0u, eacc, 4));
            eacc = hadd2(eacc, __shfl_xor_sync(~0u, eacc, 8));
            eacc = hadd2(eacc, __shfl_xor_sync(~0u, eacc, 16));
            if (lane < 4) {
                float lo, hi;
                h2f2(eacc, lo, hi);
                *(float2*)&g_epart[(size_t)ping*(NZ*BB*HW) + (zc*BB + b)*HW + n0 + lane*2] =
                    make_float2(lo, hi);
            }
        }
        if (tid < ACH && t + 1 < TT) sQf[tid] = g_QB[(b*TT + t + 1)*AA + a0 + tid];

        __threadfence();
        __syncthreads();
        if (tid == 0) {
            volatile unsigned* gp = &g_barG[b*32];
            unsigned gen = *gp;
            unsigned arrived = atomicAdd(&g_barC[b*32], 1u);
            if (arrived == NBLK_B - 1) {
                g_barC[b*32] = 0;
                __threadfence();
                *gp = gen + 1;
            } else {
                int spins = 0;
                while (*gp == gen) { __nanosleep(32); if (++spins > (1 << 23)) break; }
            }
            __threadfence();
        }
        __syncthreads();

        float e4x = 0.f, e4y = 0.f, e4z = 0.f, e4w = 0.f;
        {
            const float* base = g_epart + (size_t)ping*(NZ*BB*HW) + b*HW + tid*4;
#pragma unroll
            for (int z = 0; z < NZ; z++) {
                float4 q0 = __ldcg((const float4*)(base + (size_t)z*BB*HW));
                e4x += q0.x; e4y += q0.y; e4z += q0.z; e4w += q0.w;
            }
        }
        float4 ex;
        ex.x = __expf(e4x); ex.y = __expf(e4y); ex.z = __expf(e4z); ex.w = __expf(e4w);
        ((float4*)sE)[tid] = ex;
        float sl = ex.x + ex.y + ex.z + ex.w;
#pragma unroll
        for (int o = 16; o; o >>= 1) sl += __shfl_xor_sync(~0u, sl, o);
        if (lane == 0) reds[warp] = sl;
        __syncthreads();
        float s = ((reds[0] + reds[1]) + (reds[2] + reds[3]))
                + ((reds[4] + reds[5]) + (reds[6] + reds[7]));
        float inv = __fdividef(1.f, s);

        for (int h = tid; h < 1024; h += 256) {
            int r = h >> 6, cc = h & 63;
            sCov[r + 2][cc + 2] += sE[h] * inv;
        }
        if (zc == 0) {
            float4* ap = (float4*)(g_alpha + ((size_t)b*TT + t)*HW) + tid;
            float4 av;
            av.x = ex.x*inv; av.y = ex.y*inv; av.z = ex.z*inv; av.w = ex.w*inv;
            ap[0] = av;
        }
        __syncthreads();
    }
}

// ---------------- ctx GEMM via HMMA ----------------
__global__ void __launch_bounds__(256) ctxgemm_kernel(const float* __restrict__ enc_feat) {
    int b  = blockIdx.x;
    int t0 = blockIdx.y * 32;
    int c0 = blockIdx.z * 64;
    __shared__ unsigned sA[32][9];
    __shared__ unsigned sB[64][9];
    int tid = threadIdx.x, lane = tid & 31, warp = tid >> 5;
    int ln4 = lane & 3, lnr = lane >> 2;
    int mt = warp >> 2;
    int nb = (warp & 3) * 2;

    float acc[2][4];
#pragma unroll
    for (int nt = 0; nt < 2; nt++)
#pragma unroll
        for (int i = 0; i < 4; i++) acc[nt][i] = 0.f;

    for (int ks = 0; ks < 64; ks++) {
        int k0 = ks*16;
        __syncthreads();
        {
            int tl = tid >> 3, jp = tid & 7;
            float2 av = *(const float2*)&g_alpha[((size_t)b*TT + t0 + tl)*HW + k0 + jp*2];
            sA[tl][jp] = pk_h2(av.x, av.y);
        }
#pragma unroll
        for (int rep = 0; rep < 2; rep++) {
            int w = tid + rep*256;
            int cl = w >> 3, jp = w & 7;
            int cc = c0 + cl;
            unsigned v = 0u;
            if (cc < CE) {
                float2 f = *(const float2*)&enc_feat[((size_t)b*CE + cc)*HW + k0 + jp*2];
                v = pk_h2(f.x, f.y);
            }
            sB[cl][jp] = v;
        }
        __syncthreads();

        int rL = mt*16 + lnr, rH = rL + 8;
        unsigned a0 = sA[rL][ln4],     a1 = sA[rH][ln4];
        unsigned a2 = sA[rL][ln4 + 4], a3 = sA[rH][ln4 + 4];
#pragma unroll
        for (int nt = 0; nt < 2; nt++) {
            int cr = (nb + nt)*8 + lnr;
            unsigned b0 = sB[cr][ln4], b1 = sB[cr][ln4 + 4];
            mma16816(acc[nt][0], acc[nt][1], acc[nt][2], acc[nt][3],
                     a0, a1, a2, a3, b0, b1);
        }
    }

    int tL = t0 + mt*16 + lnr, tH = tL + 8;
#pragma unroll
    for (int nt = 0; nt < 2; nt++) {
        int cc = c0 + (nb + nt)*8 + ln4*2;
        if (cc + 1 < CE) {
            *(float2*)&g_ctxall[((size_t)b*TT + tL)*CE + cc] = make_float2(acc[nt][0], acc[nt][1]);
            *(float2*)&g_ctxall[((size_t)b*TT + tH)*CE + cc] = make_float2(acc[nt][2], acc[nt][3]);
        }
    }
}

// ---------------- final fc via HMMA ----------------
__global__ void __launch_bounds__(256) fc_kernel(const float* __restrict__ fc_b,
                                                 float* __restrict__ out) {
    int m0 = blockIdx.x * 64;
    int v0 = blockIdx.y * 64;
    __shared__ unsigned sW[64][9];
    __shared__ unsigned sI[64][9];
    __shared__ float    sY[64][65];
    int tid = threadIdx.x, lane = tid & 31, warp = tid >> 5;
    int ln4 = lane & 3, lnr = lane >> 2;
    int mt = warp >> 1;
    int nb = (warp & 1) * 4;

    float acc[4][4];
#pragma unroll
    for (int nt = 0; nt < 4; nt++)
#pragma unroll
        for (int i = 0; i < 4; i++) acc[nt][i] = 0.f;

    for (int ks = 0; ks < 41; ks++) {
        int k0 = ks*16;
        __syncthreads();
#pragma unroll
        for (int rep = 0; rep < 2; rep++) {
            int w = tid + rep*256;
            int r = w >> 3, jp = w & 7;
            sW[r][jp] = *(const unsigned*)&g_fcWh[(v0 + r)*(HID+CE) + k0 + jp*2];
        }
#pragma unroll
        for (int rep = 0; rep < 2; rep++) {
            int w = tid + rep*256;
            int r = w >> 3, jp = w & 7;
            float2 f;
            if (k0 < HID) f = *(const float2*)&g_x1[(m0 + r)*HID + k0 + jp*2];
            else          f = *(const float2*)&g_ctxall[(size_t)(m0 + r)*CE + (k0 - HID) + jp*2];
            sI[r][jp] = pk_h2(f.x, f.y);
        }
        __syncthreads();

        int rL = mt*16 + lnr, rH = rL + 8;
        unsigned a0 = sW[rL][ln4],     a1 = sW[rH][ln4];
        unsigned a2 = sW[rL][ln4 + 4], a3 = sW[rH][ln4 + 4];
#pragma unroll
        for (int nt = 0; nt < 4; nt++) {
            int mr = (nb + nt)*8 + lnr;
            unsigned b0 = sI[mr][ln4], b1 = sI[mr][ln4 + 4];
            mma16816(acc[nt][0], acc[nt][1], acc[nt][2], acc[nt][3],
                     a0, a1, a2, a3, b0, b1);
        }
    }

    {
        int rL = mt*16 + lnr, rH = rL + 8;
#pragma unroll
        for (int nt = 0; nt < 4; nt++) {
            int mc = (nb + nt)*8 + ln4*2;
            sY[rL][mc]     = acc[nt][0];
            sY[rL][mc + 1] = acc[nt][1];
            sY[rH][mc]     = acc[nt][2];
            sY[rH][mc + 1] = acc[nt][3];
        }
    }
    __syncthreads();
    for (int idx = tid; idx < 64*64; idx += 256) {
        int v = idx & 63, m = idx >> 6;
        out[(m0 + m)*VV + v0 + v] = sY[v][m] + fc_b[v0 + v];
    }
}

// ---------------- launch ----------------
extern "C" void kernel_launch(void* const* d_in, const int* in_sizes, int n_in,
                              void* d_out, int out_size) {
    const float* enc_feat = (const float*)d_in[0];
    const int*   tgt      = (const int*)  d_in[1];
    const float* embed    = (const float*)d_in[2];
    const float* w1       = (const float*)d_in[3];
    const float* b1       = (const float*)d_in[4];
    const float* w2       = (const float*)d_in[5];
    const float* b2       = (const float*)d_in[6];
    const float* w3       = (const float*)d_in[7];
    const float* b3       = (const float*)d_in[8];
    const float* W_enc    = (const float*)d_in[9];
    const float* b_enc    = (const float*)d_in[10];
    const float* W_h      = (const float*)d_in[11];
    const float* b_h      = (const float*)d_in[12];
    const float* W_cov    = (const float*)d_in[13];
    const float* b_cov    = (const float*)d_in[14];
    const float* v_attn   = (const float*)d_in[15];
    const float* fc_W     = (const float*)d_in[16];
    const float* fc_b     = (const float*)d_in[17];
    float* out = (float*)d_out;

    static cudaStream_t s2 = nullptr;
    static cudaEvent_t evFork = nullptr, evJoin = nullptr;
    if (s2 == nullptr) {
        cudaStreamCreateWithFlags(&s2, cudaStreamNonBlocking);
        cudaEventCreateWithFlags(&evFork, cudaEventDisableTiming);
        cudaEventCreateWithFlags(&evJoin, cudaEventDisableTiming);
    }

    cudaFuncSetAttribute(scan_kernel, cudaFuncAttributeMaxDynamicSharedMemorySize, SM_TOT);

    // fork: encproj depends only on raw inputs -> run concurrently on s2
    cudaEventRecord(evFork, 0);
    cudaStreamWaitEvent(s2, evFork, 0);
    encproj_kernel<<<dim3(BB, 4, 16), 256, 0, s2>>>(enc_feat, W_enc, b_enc);
    cudaEventRecord(evJoin, s2);

    prep_kernel<<<4608, 256>>>(tgt, embed, w1, w2, w3, W_h, fc_W, W_cov);

    dim3 gglu(BB, 8, 2);
    glu_kernel<<<gglu, 256>>>(0, 0, b1);   // g_x0 -> g_x1
    glu_kernel<<<gglu, 256>>>(1, 1, b2);   // g_x1 -> g_x0
    glu_kernel<<<gglu, 256>>>(0, 2, b3);   // g_x0 -> g_x1 (= hidd)

    qgemm_kernel<<<dim3(48, 4), 256>>>(b_h, b_cov);

    // join: scan needs encproj output
    cudaStreamWaitEvent(0, evJoin, 0);

    scan_kernel<<<SGRID, 256, SM_TOT>>>(v_attn);

    ctxgemm_kernel<<<dim3(BB, 3, 7), 256>>>(enc_feat);
    fc_kernel<<<dim3(48, 4), 256>>>(fc_b, out);
}